// round 2
// baseline (speedup 1.0000x reference)
#include <cuda_runtime.h>

// ---------------------------------------------------------------------------
// Problem constants
// ---------------------------------------------------------------------------
#define Bb  2
#define Ss  2048
#define Dd  2048
#define Hh  16
#define HDd 128
#define Ff  8192
#define LCc 512
#define EPSf 1e-6f

// ---------------------------------------------------------------------------
// Scratch (allocation-free rule: __device__ globals)
// ---------------------------------------------------------------------------
__device__ float g_em [Bb * 6 * Dd];                       // modulation + e
__device__ float g_tx [(size_t)Bb * Ss * Dd];              // 32 MB
__device__ float g_q  [(size_t)Bb * Ss * Dd];              // 32 MB
__device__ float g_k  [(size_t)Bb * Ss * Dd];              // 32 MB
__device__ float g_v  [(size_t)Bb * Ss * Dd];              // 32 MB
__device__ float g_y  [(size_t)Bb * Ss * Dd];              // 32 MB
__device__ float g_ffn[(size_t)Bb * Ss * Ff];              // 128 MB
__device__ float g_sc [(size_t)Bb * Hh * Ss * Ss];         // 512 MB (scores)

// ---------------------------------------------------------------------------
// Generic batched SGEMM: C = A @ B (+bias) (+gelu)
//   A: M x K, row-major, leading dim lda
//   B: if !TRANSB: K x N (ldb); if TRANSB: N x K (ldb) -> C = A @ B^T
//   batch index z -> (zb = z / Hdiv, zh = z % Hdiv), pointer offsets via strides.
//   All of M, N multiples of 128; K multiple of 8 (true for every call here).
// ---------------------------------------------------------------------------
__device__ __forceinline__ float gelu_t(float x) {
    float x3 = x * x * x;
    return 0.5f * x * (1.f + tanhf(0.7978845608028654f * (x + 0.044715f * x3)));
}

template <bool TRANSB, bool GELU>
__global__ __launch_bounds__(256, 2)
void sgemm_k(const float* __restrict__ A, const float* __restrict__ Bm,
             float* __restrict__ C, const float* __restrict__ bias,
             int M, int N, int K, int lda, int ldb, int ldc,
             long long sAb, long long sAh, long long sBb, long long sBh,
             long long sCb, long long sCh, int Hdiv)
{
    const int z  = blockIdx.z;
    const int zb = z / Hdiv;
    const int zh = z - zb * Hdiv;
    A  += zb * sAb + zh * sAh;
    Bm += zb * sBb + zh * sBh;
    C  += zb * sCb + zh * sCh;

    __shared__ __align__(16) float As[8][132];
    __shared__ __align__(16) float Bs[8][132];

    const int tid  = threadIdx.x;
    const int row0 = blockIdx.y * 128;
    const int col0 = blockIdx.x * 128;
    const int tx   = tid & 15;   // 0..15 -> 8 cols each
    const int ty   = tid >> 4;   // 0..15 -> 8 rows each

    float acc[8][8];
#pragma unroll
    for (int i = 0; i < 8; i++)
#pragma unroll
        for (int j = 0; j < 8; j++) acc[i][j] = 0.f;

    // load mappings
    const int ar = tid >> 1;          // 0..127
    const int ac = (tid & 1) * 4;     // 0 or 4
    const int br = tid >> 5;          // 0..7
    const int bc = (tid & 31) * 4;    // 0..124

    const float* Ap = A + (long long)(row0 + ar) * lda + ac;

    for (int k0 = 0; k0 < K; k0 += 8) {
        // A tile (always "row-major, K inner"): store transposed As[k][m]
        float4 av = *(const float4*)(Ap + k0);
        As[ac + 0][ar] = av.x;
        As[ac + 1][ar] = av.y;
        As[ac + 2][ar] = av.z;
        As[ac + 3][ar] = av.w;

        if (TRANSB) {
            // B is N x K; need Bs[k][n]
            const float* Bp = Bm + (long long)(col0 + ar) * ldb + k0 + ac;
            float4 bv = *(const float4*)Bp;
            Bs[ac + 0][ar] = bv.x;
            Bs[ac + 1][ar] = bv.y;
            Bs[ac + 2][ar] = bv.z;
            Bs[ac + 3][ar] = bv.w;
        } else {
            // B is K x N; Bs[k][n] contiguous along n
            const float* Bp = Bm + (long long)(k0 + br) * ldb + col0 + bc;
            *(float4*)&Bs[br][bc] = *(const float4*)Bp;
        }
        __syncthreads();

#pragma unroll
        for (int kk = 0; kk < 8; kk++) {
            float a[8], b[8];
            *(float4*)&a[0] = *(float4*)&As[kk][ty * 8];
            *(float4*)&a[4] = *(float4*)&As[kk][ty * 8 + 4];
            *(float4*)&b[0] = *(float4*)&Bs[kk][tx * 8];
            *(float4*)&b[4] = *(float4*)&Bs[kk][tx * 8 + 4];
#pragma unroll
            for (int i = 0; i < 8; i++)
#pragma unroll
                for (int j = 0; j < 8; j++)
                    acc[i][j] = fmaf(a[i], b[j], acc[i][j]);
        }
        __syncthreads();
    }

    // epilogue
    float bv[8];
    if (bias != nullptr) {
#pragma unroll
        for (int j = 0; j < 8; j++) bv[j] = bias[col0 + tx * 8 + j];
    } else {
#pragma unroll
        for (int j = 0; j < 8; j++) bv[j] = 0.f;
    }
#pragma unroll
    for (int i = 0; i < 8; i++) {
        float o[8];
#pragma unroll
        for (int j = 0; j < 8; j++) {
            float v = acc[i][j] + bv[j];
            if (GELU) v = gelu_t(v);
            o[j] = v;
        }
        float* Cp = C + (long long)(row0 + ty * 8 + i) * ldc + col0 + tx * 8;
        *(float4*)Cp       = make_float4(o[0], o[1], o[2], o[3]);
        *(float4*)(Cp + 4) = make_float4(o[4], o[5], o[6], o[7]);
    }
}

// ---------------------------------------------------------------------------
// Elementwise / normalization kernels
// ---------------------------------------------------------------------------
__global__ void k_copy(const float* __restrict__ a, float* __restrict__ o, long long n) {
    long long i = (long long)blockIdx.x * 256 + threadIdx.x;
    if (i < n) o[i] = a[i];
}

__global__ void k_emadd(const float* __restrict__ e, const float* __restrict__ mod,
                        float* __restrict__ em) {
    int i = blockIdx.x * 256 + threadIdx.x;
    if (i < Bb * 6 * Dd) em[i] = e[i] + mod[i % (6 * Dd)];
}

// out_row = LayerNorm(x_row) * (1 + em[b, scaleRow, :]) + em[b, shiftRow, :]
__global__ void k_ln_mod(const float* __restrict__ x, const float* __restrict__ em,
                         float* __restrict__ out, int scaleRow, int shiftRow) {
    int row = blockIdx.x;            // B*S rows
    int b   = row / Ss;
    const float* xr = x + (long long)row * Dd;
    float* orow     = out + (long long)row * Dd;
    const float* es = em + ((long long)b * 6 + scaleRow) * Dd;
    const float* eh = em + ((long long)b * 6 + shiftRow) * Dd;
    int t = threadIdx.x;             // 256 threads, 8 elems each
    float v[8];
    float s = 0.f, s2 = 0.f;
#pragma unroll
    for (int i = 0; i < 8; i++) {
        float u = xr[t + 256 * i];
        v[i] = u; s += u; s2 += u * u;
    }
    __shared__ float sh[512];
    sh[t] = s; sh[256 + t] = s2;
    __syncthreads();
    for (int o = 128; o > 0; o >>= 1) {
        if (t < o) { sh[t] += sh[t + o]; sh[256 + t] += sh[256 + t + o]; }
        __syncthreads();
    }
    float m   = sh[0] * (1.f / Dd);
    float var = sh[256] * (1.f / Dd) - m * m;
    float r   = rsqrtf(var + EPSf);
#pragma unroll
    for (int i = 0; i < 8; i++) {
        int d = t + 256 * i;
        orow[d] = (v[i] - m) * r * (1.f + es[d]) + eh[d];
    }
}

// x_row = x_row * rsqrt(mean(x^2)+eps) * w      (in place)
__global__ void k_rmsnorm(float* __restrict__ x, const float* __restrict__ w) {
    int row = blockIdx.x;
    float* xr = x + (long long)row * Dd;
    int t = threadIdx.x;
    float v[8];
    float s2 = 0.f;
#pragma unroll
    for (int i = 0; i < 8; i++) {
        float u = xr[t + 256 * i];
        v[i] = u; s2 += u * u;
    }
    __shared__ float sh[256];
    sh[t] = s2;
    __syncthreads();
    for (int o = 128; o > 0; o >>= 1) {
        if (t < o) sh[t] += sh[t + o];
        __syncthreads();
    }
    float r = rsqrtf(sh[0] * (1.f / Dd) + EPSf);
#pragma unroll
    for (int i = 0; i < 8; i++) {
        int d = t + 256 * i;
        xr[d] = v[i] * r * w[d];
    }
}

// In-place RoPE on (B,S,H,HD): pairs (2*d2, 2*d2+1), angle = freqs[s, d2]
__global__ void k_rope(float* __restrict__ q, const float* __restrict__ freqs) {
    long long i = (long long)blockIdx.x * 256 + threadIdx.x;
    const long long n = (long long)Bb * Ss * Hh * 64;
    if (i >= n) return;
    int d2 = (int)(i & 63);
    long long r  = i >> 6;           // (b*S + s)*H + h
    long long bs = r >> 4;           // H = 16
    int sIdx = (int)(bs % Ss);
    float sn, cs;
    __sincosf(freqs[sIdx * 64 + d2], &sn, &cs);
    long long base = r * HDd + 2 * d2;
    float xr = q[base], xi = q[base + 1];
    q[base]     = xr * cs - xi * sn;
    q[base + 1] = xr * sn + xi * cs;
}

// rowwise softmax of (scores * scale), in place
__global__ void k_softmax(float* __restrict__ S, int ncols, float scale) {
    long long row = blockIdx.x;
    float* p = S + row * (long long)ncols;
    int t = threadIdx.x;
    __shared__ float sh[256];
    float lm = -3.4e38f;
    for (int c = t; c < ncols; c += 256) lm = fmaxf(lm, p[c]);
    sh[t] = lm; __syncthreads();
    for (int o = 128; o > 0; o >>= 1) { if (t < o) sh[t] = fmaxf(sh[t], sh[t + o]); __syncthreads(); }
    float m = sh[0] * scale;
    __syncthreads();
    float ls = 0.f;
    for (int c = t; c < ncols; c += 256) {
        float e = __expf(p[c] * scale - m);
        p[c] = e; ls += e;
    }
    sh[t] = ls; __syncthreads();
    for (int o = 128; o > 0; o >>= 1) { if (t < o) sh[t] += sh[t + o]; __syncthreads(); }
    float inv = 1.f / sh[0];
    for (int c = t; c < ncols; c += 256) p[c] *= inv;
}

// x += y * em[b, gateRow, d]   (gateRow < 0: plain add)
__global__ void k_residual(float* __restrict__ x, const float* __restrict__ y,
                           const float* __restrict__ em, int gateRow) {
    long long i = (long long)blockIdx.x * 256 + threadIdx.x;
    const long long n = (long long)Bb * Ss * Dd;
    if (i >= n) return;
    if (gateRow >= 0) {
        int d = (int)(i % Dd);
        long long b = i / ((long long)Ss * Dd);
        x[i] += y[i] * em[(b * 6 + gateRow) * Dd + d];
    } else {
        x[i] += y[i];
    }
}

// ---------------------------------------------------------------------------
// Host orchestration
// ---------------------------------------------------------------------------
static inline void launch_gemm(const float* A, const float* Bm, float* C, const float* bias,
                               int M, int N, int K, int lda, int ldb, int ldc,
                               int batch, int Hdiv,
                               long long sAb, long long sAh, long long sBb, long long sBh,
                               long long sCb, long long sCh,
                               bool transb, bool gelu)
{
    dim3 g(N / 128, M / 128, batch), bl(256);
    if (transb)
        sgemm_k<true, false><<<g, bl>>>(A, Bm, C, bias, M, N, K, lda, ldb, ldc,
                                        sAb, sAh, sBb, sBh, sCb, sCh, Hdiv);
    else if (gelu)
        sgemm_k<false, true><<<g, bl>>>(A, Bm, C, bias, M, N, K, lda, ldb, ldc,
                                        sAb, sAh, sBb, sBh, sCb, sCh, Hdiv);
    else
        sgemm_k<false, false><<<g, bl>>>(A, Bm, C, bias, M, N, K, lda, ldb, ldc,
                                         sAb, sAh, sBb, sBh, sCb, sCh, Hdiv);
}

extern "C" void kernel_launch(void* const* d_in, const int* in_sizes, int n_in,
                              void* d_out, int out_size)
{
    // ---- input index mapping (detect dict order vs reference-signature order)
    // signature order: ... so_b(12), snq(13)=2048 elems, snk(14), cq_w(15)...
    // dict order:      ... so_b(12), cq_w(13)=D*D elems, ...
    bool sig = (in_sizes[13] == Dd);
    int I_snq, I_snk, I_cq_w, I_cq_b, I_ck_w, I_ck_b, I_cv_w, I_cv_b;
    int I_co_w, I_co_b, I_cnq, I_cnk, I_f1_w, I_f1_b, I_f2_w, I_f2_b;
    if (sig) {
        I_snq = 13; I_snk = 14;
        I_cq_w = 15; I_cq_b = 16; I_ck_w = 17; I_ck_b = 18;
        I_cv_w = 19; I_cv_b = 20; I_co_w = 21; I_co_b = 22;
        I_cnq = 23; I_cnk = 24;
        I_f1_w = 25; I_f1_b = 26; I_f2_w = 27; I_f2_b = 28;
    } else {
        I_cq_w = 13; I_cq_b = 14; I_ck_w = 15; I_ck_b = 16;
        I_cv_w = 17; I_cv_b = 18; I_co_w = 19; I_co_b = 20;
        I_f1_w = 21; I_f1_b = 22; I_f2_w = 23; I_f2_b = 24;
        I_snq = 25; I_snk = 26; I_cnq = 27; I_cnk = 28;
    }

    const float* x    = (const float*)d_in[0];
    const float* e    = (const float*)d_in[1];
    const float* ctx  = (const float*)d_in[2];
    const float* fr   = (const float*)d_in[3];
    const float* mod  = (const float*)d_in[4];
    const float* sq_w = (const float*)d_in[5];  const float* sq_b = (const float*)d_in[6];
    const float* sk_w = (const float*)d_in[7];  const float* sk_b = (const float*)d_in[8];
    const float* sv_w = (const float*)d_in[9];  const float* sv_b = (const float*)d_in[10];
    const float* so_w = (const float*)d_in[11]; const float* so_b = (const float*)d_in[12];
    const float* snq  = (const float*)d_in[I_snq];  const float* snk = (const float*)d_in[I_snk];
    const float* cq_w = (const float*)d_in[I_cq_w]; const float* cq_b = (const float*)d_in[I_cq_b];
    const float* ck_w = (const float*)d_in[I_ck_w]; const float* ck_b = (const float*)d_in[I_ck_b];
    const float* cv_w = (const float*)d_in[I_cv_w]; const float* cv_b = (const float*)d_in[I_cv_b];
    const float* co_w = (const float*)d_in[I_co_w]; const float* co_b = (const float*)d_in[I_co_b];
    const float* cnq  = (const float*)d_in[I_cnq];  const float* cnk = (const float*)d_in[I_cnk];
    const float* f1_w = (const float*)d_in[I_f1_w]; const float* f1_b = (const float*)d_in[I_f1_b];
    const float* f2_w = (const float*)d_in[I_f2_w]; const float* f2_b = (const float*)d_in[I_f2_b];

    float *em, *tx, *q, *k, *v, *y, *ffn, *sc;
    cudaGetSymbolAddress((void**)&em,  g_em);
    cudaGetSymbolAddress((void**)&tx,  g_tx);
    cudaGetSymbolAddress((void**)&q,   g_q);
    cudaGetSymbolAddress((void**)&k,   g_k);
    cudaGetSymbolAddress((void**)&v,   g_v);
    cudaGetSymbolAddress((void**)&y,   g_y);
    cudaGetSymbolAddress((void**)&ffn, g_ffn);
    cudaGetSymbolAddress((void**)&sc,  g_sc);

    float* xo = (float*)d_out;

    const long long NX = (long long)Bb * Ss * Dd;            // 8,388,608
    const float SCALE = 0.08838834764831845f;                // 1/sqrt(128)
    const long long SD = (long long)Ss * Dd;
    const long long SS = (long long)Ss * Ss;
    const long long SL = (long long)Ss * LCc;

    // x working copy into d_out
    k_copy<<<(int)((NX + 255) / 256), 256>>>(x, xo, NX);
    // em = modulation + e
    k_emadd<<<(Bb * 6 * Dd + 255) / 256, 256>>>(e, mod, em);

    // ===================== self attention =====================
    // tx = LN(x)*(1+e1)+e0
    k_ln_mod<<<Bb * Ss, 256>>>(x, em, tx, 1, 0);
    // q/k/v projections
    launch_gemm(tx, sq_w, q, sq_b, Bb * Ss, Dd, Dd, Dd, Dd, Dd, 1, 1, 0,0,0,0,0,0, false, false);
    launch_gemm(tx, sk_w, k, sk_b, Bb * Ss, Dd, Dd, Dd, Dd, Dd, 1, 1, 0,0,0,0,0,0, false, false);
    launch_gemm(tx, sv_w, v, sv_b, Bb * Ss, Dd, Dd, Dd, Dd, Dd, 1, 1, 0,0,0,0,0,0, false, false);
    k_rmsnorm<<<Bb * Ss, 256>>>(q, snq);
    k_rmsnorm<<<Bb * Ss, 256>>>(k, snk);
    // rope
    {
        long long n = (long long)Bb * Ss * Hh * 64;
        int gs = (int)((n + 255) / 256);
        k_rope<<<gs, 256>>>(q, fr);
        k_rope<<<gs, 256>>>(k, fr);
    }
    // scores[b,h] = Q[b,:,h,:] @ K[b,:,h,:]^T
    launch_gemm(q, k, sc, nullptr, Ss, Ss, HDd, Dd, Dd, Ss, Bb * Hh, Hh,
                SD, HDd, SD, HDd, (long long)Hh * SS, SS, true, false);
    k_softmax<<<Bb * Hh * Ss, 256>>>(sc, Ss, SCALE);
    // attn_out[b,:,h,:] = P[b,h] @ V[b,:,h,:]   -> tx
    launch_gemm(sc, v, tx, nullptr, Ss, HDd, Ss, Ss, Dd, Dd, Bb * Hh, Hh,
                (long long)Hh * SS, SS, SD, HDd, SD, HDd, false, false);
    // o projection + gated residual (e2)
    launch_gemm(tx, so_w, y, so_b, Bb * Ss, Dd, Dd, Dd, Dd, Dd, 1, 1, 0,0,0,0,0,0, false, false);
    k_residual<<<(int)((NX + 255) / 256), 256>>>(xo, y, em, 2);

    // ===================== cross attention =====================
    launch_gemm(xo, cq_w, q, cq_b, Bb * Ss, Dd, Dd, Dd, Dd, Dd, 1, 1, 0,0,0,0,0,0, false, false);
    k_rmsnorm<<<Bb * Ss, 256>>>(q, cnq);
    launch_gemm(ctx, ck_w, k, ck_b, Bb * LCc, Dd, Dd, Dd, Dd, Dd, 1, 1, 0,0,0,0,0,0, false, false);
    k_rmsnorm<<<Bb * LCc, 256>>>(k, cnk);
    launch_gemm(ctx, cv_w, v, cv_b, Bb * LCc, Dd, Dd, Dd, Dd, Dd, 1, 1, 0,0,0,0,0,0, false, false);
    // scores (S x LC)
    launch_gemm(q, k, sc, nullptr, Ss, LCc, HDd, Dd, Dd, LCc, Bb * Hh, Hh,
                SD, HDd, (long long)LCc * Dd, HDd, (long long)Hh * SL, SL, true, false);
    k_softmax<<<Bb * Hh * Ss, 256>>>(sc, LCc, SCALE);
    launch_gemm(sc, v, tx, nullptr, Ss, HDd, LCc, LCc, Dd, Dd, Bb * Hh, Hh,
                (long long)Hh * SL, SL, (long long)LCc * Dd, HDd, SD, HDd, false, false);
    launch_gemm(tx, co_w, y, co_b, Bb * Ss, Dd, Dd, Dd, Dd, Dd, 1, 1, 0,0,0,0,0,0, false, false);
    k_residual<<<(int)((NX + 255) / 256), 256>>>(xo, y, em, -1);

    // ===================== FFN =====================
    k_ln_mod<<<Bb * Ss, 256>>>(xo, em, tx, 4, 3);
    launch_gemm(tx, f1_w, ffn, f1_b, Bb * Ss, Ff, Dd, Dd, Ff, Ff, 1, 1, 0,0,0,0,0,0, false, true);
    launch_gemm(ffn, f2_w, y, f2_b, Bb * Ss, Dd, Ff, Ff, Dd, Dd, 1, 1, 0,0,0,0,0,0, false, false);
    k_residual<<<(int)((NX + 255) / 256), 256>>>(xo, y, em, 5);
}

// round 4
// speedup vs baseline: 1.9428x; 1.9428x over previous
#include <cuda_runtime.h>
#include <cuda_bf16.h>
#include <cstdint>

using bf16 = __nv_bfloat16;

#define Bb  2
#define Ss  2048
#define Dd  2048
#define Hh  16
#define HDd 128
#define Ff  8192
#define LCc 512
#define EPSf 1e-6f

// ---------------------------------------------------------------------------
// Scratch (__device__ globals; allocation-free rule)
// ---------------------------------------------------------------------------
__device__ float g_em [Bb * 6 * Dd];
__device__ float g_bqkv[3 * Dd];
__device__ float g_bkv [2 * Dd];
__device__ float g_qkv [(size_t)Bb * Ss * 3 * Dd];
__device__ float g_y   [(size_t)Bb * Ss * Dd];
__device__ float g_sc  [(size_t)Bb * Hh * Ss * Ss];

#define DECL2(nm, n) __device__ __align__(128) bf16 nm##h[(size_t)(n)]; __device__ __align__(128) bf16 nm##l[(size_t)(n)];
DECL2(g_tx, (size_t)Bb*Ss*Dd)
DECL2(g_cx, (size_t)Bb*LCc*Dd)
DECL2(g_q,  (size_t)Bb*Ss*Dd)
DECL2(g_k,  (size_t)Bb*Ss*Dd)
DECL2(g_vt, (size_t)Bb*Ss*Dd)
DECL2(g_p,  (size_t)Bb*Hh*Ss*Ss)
DECL2(g_f,  (size_t)Bb*Ss*Ff)
DECL2(g_wqkv, (size_t)3*Dd*Dd)
DECL2(g_wckv, (size_t)2*Dd*Dd)
DECL2(g_wo,   (size_t)Dd*Dd)
DECL2(g_wcq,  (size_t)Dd*Dd)
DECL2(g_wco,  (size_t)Dd*Dd)
DECL2(g_wf1,  (size_t)Ff*Dd)
DECL2(g_wf2,  (size_t)Dd*Ff)

// ---------------------------------------------------------------------------
// helpers
// ---------------------------------------------------------------------------
__device__ __forceinline__ uint32_t smem_u32(const void* p) {
    uint32_t a;
    asm("{ .reg .u64 t; cvta.to.shared.u64 t, %1; cvt.u32.u64 %0, t; }" : "=r"(a) : "l"(p));
    return a;
}
#define CP_COMMIT() asm volatile("cp.async.commit_group;" ::: "memory")

#define LDSM4(d, a) \
  asm volatile("ldmatrix.sync.aligned.m8n8.x4.shared.b16 {%0,%1,%2,%3}, [%4];" \
    : "=r"((d)[0]), "=r"((d)[1]), "=r"((d)[2]), "=r"((d)[3]) : "r"(a))

#define MMA16816(c, a, b0, b1) \
  asm volatile("mma.sync.aligned.m16n8k16.row.col.f32.bf16.bf16.f32 " \
    "{%0,%1,%2,%3}, {%4,%5,%6,%7}, {%8,%9}, {%0,%1,%2,%3};" \
    : "+f"((c)[0]), "+f"((c)[1]), "+f"((c)[2]), "+f"((c)[3]) \
    : "r"((a)[0]), "r"((a)[1]), "r"((a)[2]), "r"((a)[3]), "r"(b0), "r"(b1))

__device__ __forceinline__ float gelu_t(float x) {
    float x3 = x * x * x;
    return 0.5f * x * (1.f + tanhf(0.7978845608028654f * (x + 0.044715f * x3)));
}
__device__ __forceinline__ void split2(float v, bf16& h, bf16& l) {
    h = __float2bfloat16(v);
    l = __float2bfloat16(v - __bfloat162float(h));
}

// stage: Ah(10240) Al(10240) Bh(10240) Bl(10240); 80B row pitch, 128 rows, 32 bf16 cols
#define STAGE_BYTES 40960u
#define SMEM_TOTAL_G (4 * 40960)

// ---------------------------------------------------------------------------
// HMMA (mma.sync) GEMM: C(MxN) = A(MxK) @ B^T, B stored [N x K], bf16 hi/lo
// 3-term bf16x3 into fp32 acc. EPI: 0 fp32(+bias); 1 gelu->bf16 h/l(+bias);
// 2 xo += (acc+bias)*gate  (gateRow<0: plain add)
// ---------------------------------------------------------------------------
template <int EPI>
__global__ __launch_bounds__(256, 1)
void mma_gemm(const bf16* __restrict__ Ah, const bf16* __restrict__ Al,
              const bf16* __restrict__ Bh, const bf16* __restrict__ Bl,
              int K, int lda, int ldb,
              float* C, bf16* Ch, bf16* Cl, int ldc,
              const float* __restrict__ bias, const float* __restrict__ em, int gateRow,
              int Hdiv,
              long long sAb, long long sAh_, long long sBb, long long sBh_,
              long long sCb, long long sCh_)
{
    extern __shared__ __align__(128) char smem[];
    const uint32_t sbase = smem_u32(smem);
    const int tid = threadIdx.x;
    const int w = tid >> 5, l = tid & 31;
    const int wm = w >> 2, wn = w & 3;          // 2 x 4 warp grid, warp tile 64x32

    const int z = blockIdx.z;
    const int zb = z / Hdiv, zh = z - zb * Hdiv;
    Ah += zb * sAb + zh * sAh_;  Al += zb * sAb + zh * sAh_;
    Bh += zb * sBb + zh * sBh_;  Bl += zb * sBb + zh * sBh_;
    const long long coff = zb * sCb + zh * sCh_;
    const int m0 = blockIdx.y * 128, n0 = blockIdx.x * 128;

    float acc[4][4][4];
#pragma unroll
    for (int i = 0; i < 4; i++)
#pragma unroll
        for (int j = 0; j < 4; j++)
#pragma unroll
            for (int r = 0; r < 4; r++) acc[i][j][r] = 0.f;

    // ---- loader: one k-chunk (32 cols) of all 4 operand halves into stage
    auto load_chunk = [&](int kc, int stg) {
        const uint32_t sb = sbase + (uint32_t)stg * STAGE_BYTES;
        auto one = [&](const bf16* p, int r0, int ld, uint32_t off) {
#pragma unroll
            for (int it = 0; it < 2; it++) {
                int c = tid + it * 256;             // 0..511
                int r = c >> 2, c16 = c & 3;
                const char* g = (const char*)(p + (long long)(r0 + r) * ld + kc * 32) + c16 * 16;
                asm volatile("cp.async.cg.shared.global [%0], [%1], 16;"
                             :: "r"(sb + off + (uint32_t)(r * 80 + c16 * 16)), "l"(g));
            }
        };
        one(Ah, m0, lda, 0u);      one(Al, m0, lda, 10240u);
        one(Bh, n0, ldb, 20480u);  one(Bl, n0, ldb, 30720u);
        CP_COMMIT();
    };

    const uint32_t lrow  = (uint32_t)(l & 15) * 80u;
    const uint32_t lhalf = (uint32_t)(l >> 4) * 16u;

    auto compute = [&](int stg) {
        const uint32_t sb = sbase + (uint32_t)stg * STAGE_BYTES;
#pragma unroll
        for (int ks = 0; ks < 2; ks++) {
            const uint32_t kb = (uint32_t)ks * 32u + lhalf;
            uint32_t aH[4][4], aL[4][4], bH[2][4], bL[2][4];
#pragma unroll
            for (int mt = 0; mt < 4; mt++) {
                uint32_t ra = sb + (uint32_t)((wm * 64 + mt * 16) * 80) + lrow + kb;
                LDSM4(aH[mt], ra);
                LDSM4(aL[mt], ra + 10240u);
            }
#pragma unroll
            for (int bt = 0; bt < 2; bt++) {
                uint32_t rb = sb + 20480u + (uint32_t)((wn * 32 + bt * 16) * 80) + lrow + kb;
                LDSM4(bH[bt], rb);
                LDSM4(bL[bt], rb + 10240u);
            }
#pragma unroll
            for (int mt = 0; mt < 4; mt++)
#pragma unroll
                for (int nt = 0; nt < 4; nt++) {
                    const int bt = nt >> 1, hi = nt & 1;
                    MMA16816(acc[mt][nt], aH[mt], bH[bt][hi], bH[bt][hi + 2]);
                }
#pragma unroll
            for (int mt = 0; mt < 4; mt++)
#pragma unroll
                for (int nt = 0; nt < 4; nt++) {
                    const int bt = nt >> 1, hi = nt & 1;
                    MMA16816(acc[mt][nt], aL[mt], bH[bt][hi], bH[bt][hi + 2]);
                }
#pragma unroll
            for (int mt = 0; mt < 4; mt++)
#pragma unroll
                for (int nt = 0; nt < 4; nt++) {
                    const int bt = nt >> 1, hi = nt & 1;
                    MMA16816(acc[mt][nt], aH[mt], bL[bt][hi], bL[bt][hi + 2]);
                }
        }
    };

    const int nk = K / 32;
    load_chunk(0, 0);
    if (nk > 1) load_chunk(1, 1);
    for (int i = 0; i < nk; i++) {
        if (i + 1 < nk) asm volatile("cp.async.wait_group 1;" ::: "memory");
        else            asm volatile("cp.async.wait_group 0;" ::: "memory");
        __syncthreads();
        if (i + 2 < nk) load_chunk(i + 2, (i + 2) & 3);
        compute(i & 3);
    }

    // ---------------- epilogue ----------------
    const int r0f = l >> 2, c0f = (l & 3) * 2;
#pragma unroll
    for (int mt = 0; mt < 4; mt++) {
        const int gr = m0 + wm * 64 + mt * 16 + r0f;
#pragma unroll
        for (int nt = 0; nt < 4; nt++) {
            const int gc = n0 + wn * 32 + nt * 8 + c0f;
            float a0 = acc[mt][nt][0], a1 = acc[mt][nt][1];
            float a2 = acc[mt][nt][2], a3 = acc[mt][nt][3];
            if (EPI == 0) {
                float bx = bias ? bias[gc] : 0.f, by = bias ? bias[gc + 1] : 0.f;
                float2 u0; u0.x = a0 + bx; u0.y = a1 + by;
                float2 u1; u1.x = a2 + bx; u1.y = a3 + by;
                *(float2*)(C + coff + (long long)gr * ldc + gc) = u0;
                *(float2*)(C + coff + (long long)(gr + 8) * ldc + gc) = u1;
            } else if (EPI == 1) {
                float bx = bias[gc], by = bias[gc + 1];
                float v0 = gelu_t(a0 + bx), v1 = gelu_t(a1 + by);
                float v2 = gelu_t(a2 + bx), v3 = gelu_t(a3 + by);
                bf16 h0, l0, h1, l1;
                split2(v0, h0, l0); split2(v1, h1, l1);
                __nv_bfloat162 hh0; hh0.x = h0; hh0.y = h1;
                __nv_bfloat162 ll0; ll0.x = l0; ll0.y = l1;
                *(__nv_bfloat162*)(Ch + coff + (long long)gr * ldc + gc) = hh0;
                *(__nv_bfloat162*)(Cl + coff + (long long)gr * ldc + gc) = ll0;
                split2(v2, h0, l0); split2(v3, h1, l1);
                __nv_bfloat162 hh1; hh1.x = h0; hh1.y = h1;
                __nv_bfloat162 ll1; ll1.x = l0; ll1.y = l1;
                *(__nv_bfloat162*)(Ch + coff + (long long)(gr + 8) * ldc + gc) = hh1;
                *(__nv_bfloat162*)(Cl + coff + (long long)(gr + 8) * ldc + gc) = ll1;
            } else {
                float bx = bias[gc], by = bias[gc + 1];
#pragma unroll
                for (int hh = 0; hh < 2; hh++) {
                    const int row = gr + hh * 8;
                    float va = (hh ? a2 : a0) + bx;
                    float vb = (hh ? a3 : a1) + by;
                    if (gateRow >= 0) {
                        const int b = row / Ss;
                        const float* gp = em + ((long long)b * 6 + gateRow) * Dd;
                        va *= gp[gc]; vb *= gp[gc + 1];
                    }
                    float2 o = *(float2*)(C + coff + (long long)row * ldc + gc);
                    o.x += va; o.y += vb;
                    *(float2*)(C + coff + (long long)row * ldc + gc) = o;
                }
            }
        }
    }
}

// ---------------------------------------------------------------------------
// Elementwise kernels
// ---------------------------------------------------------------------------
__global__ void k_copy(const float* __restrict__ a, float* __restrict__ o, long long n) {
    long long i = (long long)blockIdx.x * 256 + threadIdx.x;
    if (i < n) o[i] = a[i];
}
__global__ void k_emadd(const float* __restrict__ e, const float* __restrict__ mod,
                        float* __restrict__ em) {
    int i = blockIdx.x * 256 + threadIdx.x;
    if (i < Bb * 6 * Dd) em[i] = e[i] + mod[i % (6 * Dd)];
}
__global__ void k_split4(const float* __restrict__ in, bf16* __restrict__ oh,
                         bf16* __restrict__ ol, long long n) {
    long long i = ((long long)blockIdx.x * 256 + threadIdx.x) * 4;
    if (i >= n) return;
    float4 v = *(const float4*)(in + i);
    bf16 h, l;
    split2(v.x, h, l); oh[i] = h; ol[i] = l;
    split2(v.y, h, l); oh[i + 1] = h; ol[i + 1] = l;
    split2(v.z, h, l); oh[i + 2] = h; ol[i + 2] = l;
    split2(v.w, h, l); oh[i + 3] = h; ol[i + 3] = l;
}
__global__ void k_tsplit(const float* __restrict__ W, bf16* __restrict__ Th,
                         bf16* __restrict__ Tl, int Kd, int Nd) {
    __shared__ float t[32][33];
    int n0 = blockIdx.x * 32, k0 = blockIdx.y * 32;
    for (int j = threadIdx.y; j < 32; j += 8)
        t[j][threadIdx.x] = W[(long long)(k0 + j) * Nd + n0 + threadIdx.x];
    __syncthreads();
    for (int j = threadIdx.y; j < 32; j += 8) {
        float v = t[threadIdx.x][j];
        long long o = (long long)(n0 + j) * Kd + k0 + threadIdx.x;
        bf16 h, l; split2(v, h, l);
        Th[o] = h; Tl[o] = l;
    }
}
__global__ void k_ln_mod_split(const float* __restrict__ x, const float* __restrict__ em,
                               bf16* __restrict__ oh, bf16* __restrict__ ol,
                               int scaleRow, int shiftRow) {
    int row = blockIdx.x, b = row / Ss, t = threadIdx.x;
    const float* xr = x + (long long)row * Dd;
    const float* es = em + ((long long)b * 6 + scaleRow) * Dd;
    const float* eh = em + ((long long)b * 6 + shiftRow) * Dd;
    float v[8];
    float4 a0 = *(const float4*)(xr + t * 8);
    float4 a1 = *(const float4*)(xr + t * 8 + 4);
    v[0]=a0.x; v[1]=a0.y; v[2]=a0.z; v[3]=a0.w; v[4]=a1.x; v[5]=a1.y; v[6]=a1.z; v[7]=a1.w;
    float s = 0.f, s2 = 0.f;
#pragma unroll
    for (int i = 0; i < 8; i++) { s += v[i]; s2 += v[i] * v[i]; }
    __shared__ float sh[512];
    sh[t] = s; sh[256 + t] = s2;
    __syncthreads();
    for (int o = 128; o > 0; o >>= 1) {
        if (t < o) { sh[t] += sh[t + o]; sh[256 + t] += sh[256 + t + o]; }
        __syncthreads();
    }
    float m = sh[0] * (1.f / Dd);
    float var = sh[256] * (1.f / Dd) - m * m;
    float r = rsqrtf(var + EPSf);
#pragma unroll
    for (int i = 0; i < 8; i++) {
        int dI = t * 8 + i;
        float u = (v[i] - m) * r * (1.f + es[dI]) + eh[dI];
        bf16 h, l; split2(u, h, l);
        oh[(long long)row * Dd + dI] = h;
        ol[(long long)row * Dd + dI] = l;
    }
}
__global__ void k_rms_rope_split(const float* __restrict__ in, int ldin, int off,
                                 const float* __restrict__ w, const float* __restrict__ freqs,
                                 bf16* __restrict__ oh, bf16* __restrict__ ol, int Sv) {
    int row = blockIdx.x, b = row / Sv, s = row % Sv, t = threadIdx.x;
    const float* xr = in + (long long)row * ldin + off;
    float v[8];
    float4 a0 = *(const float4*)(xr + t * 8);
    float4 a1 = *(const float4*)(xr + t * 8 + 4);
    v[0]=a0.x; v[1]=a0.y; v[2]=a0.z; v[3]=a0.w; v[4]=a1.x; v[5]=a1.y; v[6]=a1.z; v[7]=a1.w;
    float s2 = 0.f;
#pragma unroll
    for (int i = 0; i < 8; i++) s2 += v[i] * v[i];
    __shared__ float sh[256];
    sh[t] = s2;
    __syncthreads();
    for (int o = 128; o > 0; o >>= 1) {
        if (t < o) sh[t] += sh[t + o];
        __syncthreads();
    }
    float r = rsqrtf(sh[0] * (1.f / Dd) + EPSf);
    int dbase = t * 8, h = dbase >> 7, dd = dbase & 127;
    float u[8];
#pragma unroll
    for (int i = 0; i < 8; i++) u[i] = v[i] * r * w[dbase + i];
    if (freqs) {
#pragma unroll
        for (int pr = 0; pr < 4; pr++) {
            float sn, cs;
            __sincosf(freqs[s * 64 + (dd >> 1) + pr], &sn, &cs);
            float xr_ = u[2 * pr], xi = u[2 * pr + 1];
            u[2 * pr]     = xr_ * cs - xi * sn;
            u[2 * pr + 1] = xr_ * sn + xi * cs;
        }
    }
    long long ob = ((long long)(b * Hh + h) * Sv + s) * 128 + dd;
#pragma unroll
    for (int i = 0; i < 8; i++) {
        bf16 hh, ll; split2(u[i], hh, ll);
        oh[ob + i] = hh; ol[ob + i] = ll;
    }
}
__global__ void k_vt_split(const float* __restrict__ in, int ldin, int off,
                           bf16* __restrict__ oh, bf16* __restrict__ ol, int Sv) {
    __shared__ float t[32][33];
    int bh = blockIdx.z, b = bh >> 4, h = bh & 15;
    int s0 = blockIdx.x * 32, d0 = blockIdx.y * 32;
    for (int j = threadIdx.y; j < 32; j += 8)
        t[j][threadIdx.x] = in[(long long)(b * Sv + s0 + j) * ldin + off + h * 128 + d0 + threadIdx.x];
    __syncthreads();
    for (int j = threadIdx.y; j < 32; j += 8) {
        float v = t[threadIdx.x][j];
        long long o = (long long)(bh * 128 + d0 + j) * Sv + s0 + threadIdx.x;
        bf16 hh, ll; split2(v, hh, ll);
        oh[o] = hh; ol[o] = ll;
    }
}
__global__ void k_softmax_split(const float* __restrict__ S, bf16* __restrict__ oh,
                                bf16* __restrict__ ol, int ncols, float scale) {
    long long row = blockIdx.x;
    const float* p = S + row * ncols;
    bf16* Hp = oh + row * ncols;
    bf16* Lp = ol + row * ncols;
    int t = threadIdx.x, nit = ncols >> 8;
    float vv[8];
    float lm = -3.4e38f;
    for (int k = 0; k < nit; k++) { vv[k] = p[t + (k << 8)]; lm = fmaxf(lm, vv[k]); }
    __shared__ float sh[256];
    sh[t] = lm; __syncthreads();
    for (int o = 128; o > 0; o >>= 1) { if (t < o) sh[t] = fmaxf(sh[t], sh[t + o]); __syncthreads(); }
    float m = sh[0] * scale;
    __syncthreads();
    float ls = 0.f;
    for (int k = 0; k < nit; k++) { float e = __expf(vv[k] * scale - m); vv[k] = e; ls += e; }
    sh[t] = ls; __syncthreads();
    for (int o = 128; o > 0; o >>= 1) { if (t < o) sh[t] += sh[t + o]; __syncthreads(); }
    float inv = 1.f / sh[0];
    for (int k = 0; k < nit; k++) {
        bf16 h, l; split2(vv[k] * inv, h, l);
        Hp[t + (k << 8)] = h; Lp[t + (k << 8)] = l;
    }
}

// ---------------------------------------------------------------------------
// Host orchestration
// ---------------------------------------------------------------------------
static void gemm(int epi, const bf16* Ah, const bf16* Al, const bf16* Bh, const bf16* Bl,
                 int M, int N, int K, int lda, int ldb,
                 float* C, bf16* Ch, bf16* Cl, int ldc,
                 const float* bias, const float* em, int gateRow,
                 int batch, int Hdiv,
                 long long sAb, long long sAh, long long sBb, long long sBh,
                 long long sCb, long long sCh)
{
    dim3 g(N / 128, M / 128, batch), bl(256);
    size_t sm = SMEM_TOTAL_G;
    if (epi == 0)
        mma_gemm<0><<<g, bl, sm>>>(Ah, Al, Bh, Bl, K, lda, ldb, C, Ch, Cl, ldc,
                                   bias, em, gateRow, Hdiv, sAb, sAh, sBb, sBh, sCb, sCh);
    else if (epi == 1)
        mma_gemm<1><<<g, bl, sm>>>(Ah, Al, Bh, Bl, K, lda, ldb, C, Ch, Cl, ldc,
                                   bias, em, gateRow, Hdiv, sAb, sAh, sBb, sBh, sCb, sCh);
    else
        mma_gemm<2><<<g, bl, sm>>>(Ah, Al, Bh, Bl, K, lda, ldb, C, Ch, Cl, ldc,
                                   bias, em, gateRow, Hdiv, sAb, sAh, sBb, sBh, sCb, sCh);
}

#define SYM(p, s) cudaGetSymbolAddress((void**)&p, s)

extern "C" void kernel_launch(void* const* d_in, const int* in_sizes, int n_in,
                              void* d_out, int out_size)
{
    bool sig = (in_sizes[13] == Dd);
    int I_snq, I_snk, I_cq_w, I_cq_b, I_ck_w, I_ck_b, I_cv_w, I_cv_b;
    int I_co_w, I_co_b, I_cnq, I_cnk, I_f1_w, I_f1_b, I_f2_w, I_f2_b;
    if (sig) {
        I_snq=13; I_snk=14; I_cq_w=15; I_cq_b=16; I_ck_w=17; I_ck_b=18;
        I_cv_w=19; I_cv_b=20; I_co_w=21; I_co_b=22; I_cnq=23; I_cnk=24;
        I_f1_w=25; I_f1_b=26; I_f2_w=27; I_f2_b=28;
    } else {
        I_cq_w=13; I_cq_b=14; I_ck_w=15; I_ck_b=16; I_cv_w=17; I_cv_b=18;
        I_co_w=19; I_co_b=20; I_f1_w=21; I_f1_b=22; I_f2_w=23; I_f2_b=24;
        I_snq=25; I_snk=26; I_cnq=27; I_cnk=28;
    }
    const float* x    = (const float*)d_in[0];
    const float* e    = (const float*)d_in[1];
    const float* ctx  = (const float*)d_in[2];
    const float* fr   = (const float*)d_in[3];
    const float* mod  = (const float*)d_in[4];
    const float* sq_w = (const float*)d_in[5];  const float* sq_b = (const float*)d_in[6];
    const float* sk_w = (const float*)d_in[7];  const float* sk_b = (const float*)d_in[8];
    const float* sv_w = (const float*)d_in[9];  const float* sv_b = (const float*)d_in[10];
    const float* so_w = (const float*)d_in[11]; const float* so_b = (const float*)d_in[12];
    const float* snq  = (const float*)d_in[I_snq];  const float* snk  = (const float*)d_in[I_snk];
    const float* cq_w = (const float*)d_in[I_cq_w]; const float* cq_b = (const float*)d_in[I_cq_b];
    const float* ck_w = (const float*)d_in[I_ck_w]; const float* ck_b = (const float*)d_in[I_ck_b];
    const float* cv_w = (const float*)d_in[I_cv_w]; const float* cv_b = (const float*)d_in[I_cv_b];
    const float* co_w = (const float*)d_in[I_co_w]; const float* co_b = (const float*)d_in[I_co_b];
    const float* cnq  = (const float*)d_in[I_cnq];  const float* cnk  = (const float*)d_in[I_cnk];
    const float* f1_w = (const float*)d_in[I_f1_w]; const float* f1_b = (const float*)d_in[I_f1_b];
    const float* f2_w = (const float*)d_in[I_f2_w]; const float* f2_b = (const float*)d_in[I_f2_b];

    cudaFuncSetAttribute(mma_gemm<0>, cudaFuncAttributeMaxDynamicSharedMemorySize, SMEM_TOTAL_G);
    cudaFuncSetAttribute(mma_gemm<1>, cudaFuncAttributeMaxDynamicSharedMemorySize, SMEM_TOTAL_G);
    cudaFuncSetAttribute(mma_gemm<2>, cudaFuncAttributeMaxDynamicSharedMemorySize, SMEM_TOTAL_G);

    float *em_, *bqkv, *bkv, *qkv, *y, *sc;
    SYM(em_, g_em); SYM(bqkv, g_bqkv); SYM(bkv, g_bkv);
    SYM(qkv, g_qkv); SYM(y, g_y); SYM(sc, g_sc);
    bf16 *txh, *txl, *cxh, *cxl, *qh, *ql, *kh, *kl, *vth, *vtl, *ph_, *pl_, *fh, *fl;
    SYM(txh, g_txh); SYM(txl, g_txl); SYM(cxh, g_cxh); SYM(cxl, g_cxl);
    SYM(qh, g_qh); SYM(ql, g_ql); SYM(kh, g_kh); SYM(kl, g_kl);
    SYM(vth, g_vth); SYM(vtl, g_vtl); SYM(ph_, g_ph); SYM(pl_, g_pl);
    SYM(fh, g_fh); SYM(fl, g_fl);
    bf16 *wqkvh, *wqkvl, *wckvh, *wckvl, *woh, *wol, *wcqh, *wcql, *wcoh, *wcol, *wf1h, *wf1l, *wf2h, *wf2l;
    SYM(wqkvh, g_wqkvh); SYM(wqkvl, g_wqkvl); SYM(wckvh, g_wckvh); SYM(wckvl, g_wckvl);
    SYM(woh, g_woh); SYM(wol, g_wol); SYM(wcqh, g_wcqh); SYM(wcql, g_wcql);
    SYM(wcoh, g_wcoh); SYM(wcol, g_wcol); SYM(wf1h, g_wf1h); SYM(wf1l, g_wf1l);
    SYM(wf2h, g_wf2h); SYM(wf2l, g_wf2l);

    float* xo = (float*)d_out;
    const long long NX = (long long)Bb * Ss * Dd;
    const long long DD = (long long)Dd * Dd;
    const long long SD = (long long)Ss * Dd;
    const long long SS2 = (long long)Ss * Ss;
    const long long SL = (long long)Ss * LCc;
    const float SCALE = 0.08838834764831845f;
    dim3 tb(32, 8);

    // ---- prep
    k_copy<<<(int)((NX + 255) / 256), 256>>>(x, xo, NX);
    k_emadd<<<(Bb * 6 * Dd + 255) / 256, 256>>>(e, mod, em_);
    k_tsplit<<<dim3(Dd/32, Dd/32), tb>>>(sq_w, wqkvh,          wqkvl,          Dd, Dd);
    k_tsplit<<<dim3(Dd/32, Dd/32), tb>>>(sk_w, wqkvh + DD,     wqkvl + DD,     Dd, Dd);
    k_tsplit<<<dim3(Dd/32, Dd/32), tb>>>(sv_w, wqkvh + 2 * DD, wqkvl + 2 * DD, Dd, Dd);
    k_tsplit<<<dim3(Dd/32, Dd/32), tb>>>(so_w, woh,  wol,  Dd, Dd);
    k_tsplit<<<dim3(Dd/32, Dd/32), tb>>>(cq_w, wcqh, wcql, Dd, Dd);
    k_tsplit<<<dim3(Dd/32, Dd/32), tb>>>(ck_w, wckvh,      wckvl,      Dd, Dd);
    k_tsplit<<<dim3(Dd/32, Dd/32), tb>>>(cv_w, wckvh + DD, wckvl + DD, Dd, Dd);
    k_tsplit<<<dim3(Dd/32, Dd/32), tb>>>(co_w, wcoh, wcol, Dd, Dd);
    k_tsplit<<<dim3(Ff/32, Dd/32), tb>>>(f1_w, wf1h, wf1l, Dd, Ff);
    k_tsplit<<<dim3(Dd/32, Ff/32), tb>>>(f2_w, wf2h, wf2l, Ff, Dd);
    k_copy<<<(Dd + 255) / 256, 256>>>(sq_b, bqkv, Dd);
    k_copy<<<(Dd + 255) / 256, 256>>>(sk_b, bqkv + Dd, Dd);
    k_copy<<<(Dd + 255) / 256, 256>>>(sv_b, bqkv + 2 * Dd, Dd);
    k_copy<<<(Dd + 255) / 256, 256>>>(ck_b, bkv, Dd);
    k_copy<<<(Dd + 255) / 256, 256>>>(cv_b, bkv + Dd, Dd);

    // ===================== self attention =====================
    k_ln_mod_split<<<Bb * Ss, 256>>>(x, em_, txh, txl, 1, 0);
    gemm(0, txh, txl, wqkvh, wqkvl, Bb*Ss, 3*Dd, Dd, Dd, Dd,
         qkv, nullptr, nullptr, 3*Dd, bqkv, nullptr, -1, 1, 1, 0,0,0,0,0,0);
    k_rms_rope_split<<<Bb * Ss, 256>>>(qkv, 3*Dd, 0,  snq, fr, qh, ql, Ss);
    k_rms_rope_split<<<Bb * Ss, 256>>>(qkv, 3*Dd, Dd, snk, fr, kh, kl, Ss);
    k_vt_split<<<dim3(Ss/32, 4, Bb*Hh), tb>>>(qkv, 3*Dd, 2*Dd, vth, vtl, Ss);
    gemm(0, qh, ql, kh, kl, Ss, Ss, HDd, HDd, HDd,
         sc, nullptr, nullptr, Ss, nullptr, nullptr, -1, Bb*Hh, 1,
         (long long)Ss*HDd, 0, (long long)Ss*HDd, 0, SS2, 0);
    k_softmax_split<<<Bb * Hh * Ss, 256>>>(sc, ph_, pl_, Ss, SCALE);
    gemm(0, ph_, pl_, vth, vtl, Ss, HDd, Ss, Ss, Ss,
         y, nullptr, nullptr, Dd, nullptr, nullptr, -1, Bb*Hh, Hh,
         (long long)Hh*SS2, SS2, (long long)Hh*HDd*Ss, (long long)HDd*Ss, SD, HDd);
    k_split4<<<(int)(NX / 1024), 256>>>(y, txh, txl, NX);
    gemm(2, txh, txl, woh, wol, Bb*Ss, Dd, Dd, Dd, Dd,
         xo, nullptr, nullptr, Dd, so_b, em_, 2, 1, 1, 0,0,0,0,0,0);

    // ===================== cross attention =====================
    k_split4<<<(int)(NX / 1024), 256>>>(xo, txh, txl, NX);
    gemm(0, txh, txl, wcqh, wcql, Bb*Ss, Dd, Dd, Dd, Dd,
         qkv, nullptr, nullptr, Dd, cq_b, nullptr, -1, 1, 1, 0,0,0,0,0,0);
    k_rms_rope_split<<<Bb * Ss, 256>>>(qkv, Dd, 0, cnq, nullptr, qh, ql, Ss);
    k_split4<<<(int)((long long)Bb*LCc*Dd / 1024), 256>>>(ctx, cxh, cxl, (long long)Bb*LCc*Dd);
    gemm(0, cxh, cxl, wckvh, wckvl, Bb*LCc, 2*Dd, Dd, Dd, Dd,
         qkv, nullptr, nullptr, 2*Dd, bkv, nullptr, -1, 1, 1, 0,0,0,0,0,0);
    k_rms_rope_split<<<Bb * LCc, 256>>>(qkv, 2*Dd, 0, cnk, nullptr, kh, kl, LCc);
    k_vt_split<<<dim3(LCc/32, 4, Bb*Hh), tb>>>(qkv, 2*Dd, Dd, vth, vtl, LCc);
    gemm(0, qh, ql, kh, kl, Ss, LCc, HDd, HDd, HDd,
         sc, nullptr, nullptr, LCc, nullptr, nullptr, -1, Bb*Hh, 1,
         (long long)Ss*HDd, 0, (long long)LCc*HDd, 0, SL, 0);
    k_softmax_split<<<Bb * Hh * Ss, 256>>>(sc, ph_, pl_, LCc, SCALE);
    gemm(0, ph_, pl_, vth, vtl, Ss, HDd, LCc, LCc, LCc,
         y, nullptr, nullptr, Dd, nullptr, nullptr, -1, Bb*Hh, Hh,
         (long long)Hh*SL, SL, (long long)Hh*HDd*LCc, (long long)HDd*LCc, SD, HDd);
    k_split4<<<(int)(NX / 1024), 256>>>(y, txh, txl, NX);
    gemm(2, txh, txl, wcoh, wcol, Bb*Ss, Dd, Dd, Dd, Dd,
         xo, nullptr, nullptr, Dd, co_b, em_, -1, 1, 1, 0,0,0,0,0,0);

    // ===================== FFN =====================
    k_ln_mod_split<<<Bb * Ss, 256>>>(xo, em_, txh, txl, 4, 3);
    gemm(1, txh, txl, wf1h, wf1l, Bb*Ss, Ff, Dd, Dd, Dd,
         nullptr, fh, fl, Ff, f1_b, nullptr, -1, 1, 1, 0,0,0,0,0,0);
    gemm(2, fh, fl, wf2h, wf2l, Bb*Ss, Dd, Ff, Ff, Ff,
         xo, nullptr, nullptr, Dd, f2_b, em_, 5, 1, 1, 0,0,0,0,0,0);
}